// round 2
// baseline (speedup 1.0000x reference)
#include <cuda_runtime.h>

// EmbeddedGCN split into two kernels:
//  K1 (pooling, DRAM-bound):  s[b,i,f] = sum_j adj[b,i,j] * x[b,i,j,f]
//                             deg[b,i] = sum_j adj[b,i,j]
//     x = concat(sfeats1, sfeats2). One warp per (b,i) row, no smem, no syncs.
//  K2 (tiny GEMM):            out[b,i,o] = relu(s[b,i,:] @ W[:,o] + bias[o]*deg[b,i])
//
// Shapes: B=16, M=128, FE=64 per half, FTOT=128, FOUT=128. NROWS = B*M = 2048.

#define BDIM 16
#define MDIM 128
#define FE   64
#define FTOT 128
#define FOUT 128
#define NROWS (BDIM * MDIM)        // 2048

// scratch (allocation-free: device globals)
__device__ float g_s[NROWS * FTOT];    // 1 MB pooled features
__device__ float g_deg[NROWS];         // row degrees

// ---------------------------------------------------------------------------
// K1: one warp per row. Lane fg owns feature-group fg (float4):
//     fg in [0,16)  -> sf1 float4 #fg
//     fg in [16,32) -> sf2 float4 #(fg-16)
// Warp streams 32KB contiguous from sf1 + 32KB from sf2 per row.
// adjacency row (128 floats) preloaded into 4 regs/lane, broadcast via shfl.
// ---------------------------------------------------------------------------
#define K1_WARPS 4                     // rows per block
#define K1_THREADS (K1_WARPS * 32)

__global__ __launch_bounds__(K1_THREADS)
void gcn_pool_kernel(const float* __restrict__ sf1,
                     const float* __restrict__ sf2,
                     const float* __restrict__ adj)
{
    const int lane = threadIdx.x & 31;
    const int row  = blockIdx.x * K1_WARPS + (threadIdx.x >> 5);   // (b*M + i)
    if (row >= NROWS) return;

    const long rowOff = (long)row * MDIM;                // in j units

    // preload adjacency row: lane holds adj[row, lane + 32*c] for c=0..3
    float aR[4];
    #pragma unroll
    for (int c = 0; c < 4; ++c)
        aR[c] = adj[rowOff + c * 32 + lane];

    // feature source pointer for this lane (float4 units)
    const float4* src = (lane < 16)
        ? (const float4*)sf1 + rowOff * (FE / 4) + lane
        : (const float4*)sf2 + rowOff * (FE / 4) + (lane - 16);

    float4 acc = make_float4(0.f, 0.f, 0.f, 0.f);

    #pragma unroll
    for (int c = 0; c < 4; ++c) {
        const float a = aR[c];
        #pragma unroll
        for (int jj = 0; jj < 32; ++jj) {
            const float aj = __shfl_sync(0xffffffffu, a, jj);
            const float4 v = __ldg(src + (long)(c * 32 + jj) * (FE / 4));
            acc.x = fmaf(aj, v.x, acc.x);
            acc.y = fmaf(aj, v.y, acc.y);
            acc.z = fmaf(aj, v.z, acc.z);
            acc.w = fmaf(aj, v.w, acc.w);
        }
    }

    // store pooled features: group index == lane (matches concat layout)
    ((float4*)g_s)[row * (FTOT / 4) + lane] = acc;

    // degree = sum of adjacency row
    float d = aR[0] + aR[1] + aR[2] + aR[3];
    #pragma unroll
    for (int o = 16; o > 0; o >>= 1)
        d += __shfl_xor_sync(0xffffffffu, d, o);
    if (lane == 0) g_deg[row] = d;
}

// ---------------------------------------------------------------------------
// K2: tiny GEMM. 128 blocks x 256 threads; each block does 16 rows.
// W (64KB) staged in smem; s tile (16x128 = 8KB) staged in smem.
// Warp w handles rows {2w, 2w+1}; lane computes 4 outputs (float4 of W row).
// ---------------------------------------------------------------------------
#define K2_ROWS 16
#define K2_THREADS 256
#define K2_BLOCKS (NROWS / K2_ROWS)    // 128
#define K2_SMEM_FLOATS (FTOT * FOUT + K2_ROWS * FTOT)   // 16384 + 2048

__global__ __launch_bounds__(K2_THREADS)
void gcn_gemm_kernel(const float* __restrict__ weight,
                     const float* __restrict__ bias,
                     float* __restrict__ out)
{
    extern __shared__ float smem[];
    float* Wsh = smem;                     // 16384 floats
    float* Ssh = Wsh + FTOT * FOUT;        // 2048 floats

    const int tid  = threadIdx.x;
    const int wid  = tid >> 5;
    const int lane = tid & 31;
    const int row0 = blockIdx.x * K2_ROWS;

    // stage W (vectorized)
    {
        const float4* Wg4 = (const float4*)weight;
        float4*       Ws4 = (float4*)Wsh;
        #pragma unroll
        for (int k = 0; k < (FTOT * FOUT / 4) / K2_THREADS; ++k)
            Ws4[tid + k * K2_THREADS] = Wg4[tid + k * K2_THREADS];
    }
    // stage s tile (16 rows x 128 feats = 512 float4)
    {
        const float4* Sg4 = (const float4*)g_s + (long)row0 * (FTOT / 4);
        float4*       Ss4 = (float4*)Ssh;
        #pragma unroll
        for (int k = 0; k < (K2_ROWS * FTOT / 4) / K2_THREADS; ++k)
            Ss4[tid + k * K2_THREADS] = Sg4[tid + k * K2_THREADS];
    }
    __syncthreads();

    const float4* Ws4 = (const float4*)Wsh;
    const float4  bb  = ((const float4*)bias)[lane];
    float4*       out4 = (float4*)out;

    #pragma unroll
    for (int rr = 0; rr < 2; ++rr) {
        const int  lr = wid * 2 + rr;          // local row 0..15
        const int  row = row0 + lr;
        const float* sr = Ssh + lr * FTOT;

        float4 acc = make_float4(0.f, 0.f, 0.f, 0.f);
        #pragma unroll
        for (int f = 0; f < FTOT; ++f) {
            const float sv = sr[f];                    // LDS broadcast
            const float4 w = Ws4[f * (FOUT / 4) + lane];
            acc.x = fmaf(sv, w.x, acc.x);
            acc.y = fmaf(sv, w.y, acc.y);
            acc.z = fmaf(sv, w.z, acc.z);
            acc.w = fmaf(sv, w.w, acc.w);
        }
        const float d = g_deg[row];
        acc.x = fmaxf(fmaf(bb.x, d, acc.x), 0.f);
        acc.y = fmaxf(fmaf(bb.y, d, acc.y), 0.f);
        acc.z = fmaxf(fmaf(bb.z, d, acc.z), 0.f);
        acc.w = fmaxf(fmaf(bb.w, d, acc.w), 0.f);

        out4[(long)row * (FOUT / 4) + lane] = acc;
    }
}

extern "C" void kernel_launch(void* const* d_in, const int* in_sizes, int n_in,
                              void* d_out, int out_size)
{
    const float* sf1    = (const float*)d_in[0];
    const float* sf2    = (const float*)d_in[1];
    const float* adj    = (const float*)d_in[2];
    const float* weight = (const float*)d_in[3];
    const float* bias   = (const float*)d_in[4];
    float* out          = (float*)d_out;

    const int k1_grid = NROWS / K1_WARPS;   // 512 blocks
    gcn_pool_kernel<<<k1_grid, K1_THREADS>>>(sf1, sf2, adj);

    const int k2_smem = K2_SMEM_FLOATS * (int)sizeof(float);
    cudaFuncSetAttribute(gcn_gemm_kernel,
                         cudaFuncAttributeMaxDynamicSharedMemorySize, k2_smem);
    gcn_gemm_kernel<<<K2_BLOCKS, K2_THREADS, k2_smem>>>(weight, bias, out);
}

// round 3
// speedup vs baseline: 1.7019x; 1.7019x over previous
#include <cuda_runtime.h>

// EmbeddedGCN fused, warp-per-row:
//   s[b,i,f]   = sum_j adj[b,i,j] * x[b,i,j,f]      (x = concat(sf1, sf2))
//   out[b,i,o] = relu( s[b,i,:] @ W[:,o] + bias[o] * deg[b,i] )
//
// Shapes: B=16, M=128, FE=64 per half, FTOT=128, FOUT=128, NROWS=2048.
// Grid: 512 blocks x 128 threads; warp w owns row blockIdx.x*4 + w.
// Pooling: per lane 128 independent float4 loads (batched 8-deep), adjacency
// broadcast from per-warp smem slice. ONE __syncthreads per block (W staging).

#define MDIM 128
#define FE   64
#define FTOT 128
#define FOUT 128
#define NROWS 2048
#define ROWS 4
#define NT   128

// smem floats: W 16384 + adj 4*128 + s 4*128
#define SMEM_FLOATS (FTOT * FOUT + ROWS * MDIM + ROWS * FTOT)

__device__ __forceinline__ float4 f4fma(float4 acc, float a, float4 v) {
    acc.x = fmaf(a, v.x, acc.x);
    acc.y = fmaf(a, v.y, acc.y);
    acc.z = fmaf(a, v.z, acc.z);
    acc.w = fmaf(a, v.w, acc.w);
    return acc;
}

__global__ __launch_bounds__(NT)
void gcn_fused2_kernel(const float* __restrict__ sf1,
                       const float* __restrict__ sf2,
                       const float* __restrict__ adj,
                       const float* __restrict__ weight,
                       const float* __restrict__ bias,
                       float* __restrict__ out)
{
    extern __shared__ float smem[];
    float* Wsh  = smem;                          // 16384
    float* adjs = Wsh + FTOT * FOUT;             // ROWS*128
    float* Ssh  = adjs + ROWS * MDIM;            // ROWS*128

    const int tid  = threadIdx.x;
    const int w    = tid >> 5;                   // warp = local row 0..3
    const int lane = tid & 31;
    const int row  = blockIdx.x * ROWS + w;      // global (b*M + i)
    const long rowOff = (long)row * MDIM;        // j units

    // ---- stage W into smem (64 KB); no sync yet (not needed until epilogue)
    {
        const float4* Wg4 = (const float4*)weight;
        float4*       Ws4 = (float4*)Wsh;
        #pragma unroll 4
        for (int k = 0; k < (FTOT * FOUT / 4) / NT; ++k)   // 32 iters
            Ws4[tid + k * NT] = Wg4[tid + k * NT];
    }

    // ---- per-warp adjacency preload + degree ----
    float* adjw = adjs + w * MDIM;
    float a0 = adj[rowOff + lane];
    float a1 = adj[rowOff + lane + 32];
    float a2 = adj[rowOff + lane + 64];
    float a3 = adj[rowOff + lane + 96];
    adjw[lane]      = a0;
    adjw[lane + 32] = a1;
    adjw[lane + 64] = a2;
    adjw[lane + 96] = a3;
    __syncwarp();

    float deg = a0 + a1 + a2 + a3;
    #pragma unroll
    for (int o = 16; o > 0; o >>= 1)
        deg += __shfl_xor_sync(0xffffffffu, deg, o);

    // ---- pooling: lane fg owns feature-group fg; stream all 128 j ----
    const float4* src = (lane < 16)
        ? (const float4*)sf1 + rowOff * (FE / 4) + lane
        : (const float4*)sf2 + rowOff * (FE / 4) + (lane - 16);

    float4 acc = make_float4(0.f, 0.f, 0.f, 0.f);

    #pragma unroll 2
    for (int j0 = 0; j0 < MDIM; j0 += 8) {
        float4 v[8];
        float  a[8];
        #pragma unroll
        for (int u = 0; u < 8; ++u) {
            v[u] = __ldg(src + (long)(j0 + u) * (FE / 4));
            a[u] = adjw[j0 + u];
        }
        #pragma unroll
        for (int u = 0; u < 8; ++u)
            acc = f4fma(acc, a[u], v[u]);
    }

    // park pooled row in smem for the epilogue
    ((float4*)(Ssh + w * FTOT))[lane] = acc;

    __syncthreads();   // W staged + own s visible (same warp anyway)

    // ---- epilogue: warp w computes out[row, :]; lane -> outputs [4L,4L+4) ----
    {
        const float*  srow = Ssh + w * FTOT;
        const float4* Ws4  = (const float4*)Wsh;
        const float4  bb   = ((const float4*)bias)[lane];

        float4 o4 = make_float4(0.f, 0.f, 0.f, 0.f);
        #pragma unroll 8
        for (int f = 0; f < FTOT; ++f) {
            const float sv = srow[f];                  // LDS broadcast
            o4 = f4fma(o4, sv, Ws4[f * (FOUT / 4) + lane]);
        }
        o4.x = fmaxf(fmaf(bb.x, deg, o4.x), 0.f);
        o4.y = fmaxf(fmaf(bb.y, deg, o4.y), 0.f);
        o4.z = fmaxf(fmaf(bb.z, deg, o4.z), 0.f);
        o4.w = fmaxf(fmaf(bb.w, deg, o4.w), 0.f);

        ((float4*)out)[(long)row * (FOUT / 4) + lane] = o4;
    }
}

extern "C" void kernel_launch(void* const* d_in, const int* in_sizes, int n_in,
                              void* d_out, int out_size)
{
    const float* sf1    = (const float*)d_in[0];
    const float* sf2    = (const float*)d_in[1];
    const float* adj    = (const float*)d_in[2];
    const float* weight = (const float*)d_in[3];
    const float* bias   = (const float*)d_in[4];
    float* out          = (float*)d_out;

    const int smemBytes = SMEM_FLOATS * (int)sizeof(float);
    cudaFuncSetAttribute(gcn_fused2_kernel,
                         cudaFuncAttributeMaxDynamicSharedMemorySize, smemBytes);

    gcn_fused2_kernel<<<NROWS / ROWS, NT, smemBytes>>>(sf1, sf2, adj, weight, bias, out);
}

// round 5
// speedup vs baseline: 1.8696x; 1.0985x over previous
#include <cuda_runtime.h>

// EmbeddedGCN fused, high-occupancy:
//   s[b,i,f]   = sum_j adj[b,i,j] * x[b,i,j,f]   (x = concat(sf1,sf2), f<128)
//   out[b,i,o] = relu( s[b,i,:] @ W[:,o] + bias[o] * deg[b,i] )
//
// Grid 1024 x 256 threads. Block owns 2 rows; warp w: r=w>>2, c=w&3 covers
// j in [c*32, c*32+32). No W in smem (L2-resident). smem ~5KB -> 6 blocks/SM,
// 48 warps/SM. Pooling: batches of 4 independent LDG.128 per lane.

#define MDIM 128
#define FE   64
#define FTOT 128
#define FOUT 128
#define NROWS 2048
#define ROWS_PER_BLK 2
#define NT 256

__device__ __forceinline__ float4 f4fma(float4 acc, float a, float4 v) {
    acc.x = fmaf(a, v.x, acc.x);
    acc.y = fmaf(a, v.y, acc.y);
    acc.z = fmaf(a, v.z, acc.z);
    acc.w = fmaf(a, v.w, acc.w);
    return acc;
}

__global__ __launch_bounds__(NT, 6)
void gcn_fused3_kernel(const float* __restrict__ sf1,
                       const float* __restrict__ sf2,
                       const float* __restrict__ adj,
                       const float* __restrict__ weight,
                       const float* __restrict__ bias,
                       float* __restrict__ out)
{
    __shared__ float part[ROWS_PER_BLK * 4 * FTOT];   // 4KB: per (row,chunk) partial
    __shared__ float Ssh[ROWS_PER_BLK * FTOT];        // 1KB: reduced pooled rows
    __shared__ float degp[ROWS_PER_BLK * 4];          // chunk degrees
    __shared__ float degS[ROWS_PER_BLK];

    const int tid  = threadIdx.x;
    const int w    = tid >> 5;          // 0..7
    const int lane = tid & 31;
    const int r    = w >> 2;            // 0..1  local row
    const int c    = w & 3;             // 0..3  j-chunk

    const int row0 = blockIdx.x * ROWS_PER_BLK;
    const int row  = row0 + r;
    const long rowOff = (long)row * MDIM;       // j units

    // ---- adjacency chunk into regs; chunk degree ----
    const float aR = adj[rowOff + c * 32 + lane];
    {
        float d = aR;
        #pragma unroll
        for (int o = 16; o > 0; o >>= 1)
            d += __shfl_xor_sync(0xffffffffu, d, o);
        if (lane == 0) degp[r * 4 + c] = d;
    }

    // ---- pooling: lane = feature-group (float4); j in [c*32, c*32+32) ----
    const float4* src = (lane < 16)
        ? (const float4*)sf1 + rowOff * (FE / 4) + lane
        : (const float4*)sf2 + rowOff * (FE / 4) + (lane - 16);

    float4 acc = make_float4(0.f, 0.f, 0.f, 0.f);
    #pragma unroll
    for (int b = 0; b < 8; ++b) {
        float4 v[4];
        float  a[4];
        #pragma unroll
        for (int u = 0; u < 4; ++u) {
            const int jj = b * 4 + u;                     // 0..31 in chunk
            v[u] = __ldg(src + (long)(c * 32 + jj) * (FE / 4));
            a[u] = __shfl_sync(0xffffffffu, aR, jj);
        }
        #pragma unroll
        for (int u = 0; u < 4; ++u)
            acc = f4fma(acc, a[u], v[u]);
    }
    ((float4*)part)[(r * 4 + c) * (FTOT / 4) + lane] = acc;

    __syncthreads();

    // ---- reduce 4 chunk-partials per (row,f); also degrees ----
    {
        const int r2 = tid >> 7;            // 0..1
        const int f  = tid & 127;
        float s = part[(r2 * 4 + 0) * FTOT + f]
                + part[(r2 * 4 + 1) * FTOT + f]
                + part[(r2 * 4 + 2) * FTOT + f]
                + part[(r2 * 4 + 3) * FTOT + f];
        Ssh[r2 * FTOT + f] = s;
        if (tid < ROWS_PER_BLK)
            degS[tid] = degp[tid * 4 + 0] + degp[tid * 4 + 1]
                      + degp[tid * 4 + 2] + degp[tid * 4 + 3];
    }
    __syncthreads();

    // ---- epilogue: warps 0..3, q = w; lane -> output col o = q*32+lane.
    //      W streamed from L2; 2 rows per warp (2 FMA per W load). ----
    if (w < 4) {
        const int o  = w * 32 + lane;
        const float bb = __ldg(bias + o);

        float acc0 = 0.f, acc1 = 0.f;
        #pragma unroll 4
        for (int f = 0; f < FTOT; ++f) {
            const float wv = __ldg(weight + f * FOUT + o);
            acc0 = fmaf(Ssh[f],        wv, acc0);
            acc1 = fmaf(Ssh[FTOT + f], wv, acc1);
        }
        const float d0 = degS[0], d1 = degS[1];
        out[(long)row0 * FOUT + o]        = fmaxf(fmaf(bb, d0, acc0), 0.f);
        out[(long)(row0 + 1) * FOUT + o]  = fmaxf(fmaf(bb, d1, acc1), 0.f);
    }
}

extern "C" void kernel_launch(void* const* d_in, const int* in_sizes, int n_in,
                              void* d_out, int out_size)
{
    const float* sf1    = (const float*)d_in[0];
    const float* sf2    = (const float*)d_in[1];
    const float* adj    = (const float*)d_in[2];
    const float* weight = (const float*)d_in[3];
    const float* bias   = (const float*)d_in[4];
    float* out          = (float*)d_out;

    gcn_fused3_kernel<<<NROWS / ROWS_PER_BLK, NT>>>(sf1, sf2, adj, weight, bias, out);
}

// round 7
// speedup vs baseline: 7.1295x; 3.8135x over previous
#include <cuda_runtime.h>

// EmbeddedGCN fused, sparsity-aware:
//   adjacency is (exactly) 0.0 or nonzero; terms with a==0.0f contribute
//   exactly 0 to sum_j a_j*x_j, so we only load x rows where a!=0 (~25%).
//   s[b,i,f]   = sum_{j: a!=0} adj[b,i,j] * x[b,i,j,f]
//   out[b,i,o] = relu( s @ W[:,o] + bias[o]*deg )
//
// Grid 512 x 256. Block owns 4 rows. Warp w: row r=w>>1, j-half c=w&1.
// Ballot masks select nonzero j; loads batched 4-deep. Epilogue: each W
// element loaded once per block, reused for 4 rows.

#define MDIM 128
#define FE   64
#define FTOT 128
#define FOUT 128
#define NROWS 2048
#define ROWS 4
#define NT   256
#define FULLMASK 0xffffffffu

__device__ __forceinline__ float4 f4fma(float4 acc, float a, float4 v) {
    acc.x = fmaf(a, v.x, acc.x);
    acc.y = fmaf(a, v.y, acc.y);
    acc.z = fmaf(a, v.z, acc.z);
    acc.w = fmaf(a, v.w, acc.w);
    return acc;
}

__global__ __launch_bounds__(NT, 5)
void gcn_sparse_kernel(const float* __restrict__ sf1,
                       const float* __restrict__ sf2,
                       const float* __restrict__ adj,
                       const float* __restrict__ weight,
                       const float* __restrict__ bias,
                       float* __restrict__ out)
{
    __shared__ float part[2 * ROWS * FTOT];   // 4KB: pool partials, then epi partials
    __shared__ float Ssh[ROWS * FTOT];        // 2KB: pooled rows
    __shared__ float degp[ROWS * 2];
    __shared__ float degS[ROWS];

    const int tid  = threadIdx.x;
    const int w    = tid >> 5;
    const int lane = tid & 31;
    const int r    = w >> 1;                  // local row 0..3
    const int c    = w & 1;                   // j-half
    const int row0 = blockIdx.x * ROWS;
    const int row  = row0 + r;
    const long rowOff = (long)row * MDIM;
    const int jbase = c * 64;

    // ---- adjacency half-row into regs; degree partial; nonzero masks ----
    const float a0 = adj[rowOff + jbase + lane];
    const float a1 = adj[rowOff + jbase + 32 + lane];
    {
        float d = a0 + a1;
        #pragma unroll
        for (int o = 16; o > 0; o >>= 1)
            d += __shfl_xor_sync(FULLMASK, d, o);
        if (lane == 0) degp[r * 2 + c] = d;
    }
    const unsigned m0 = __ballot_sync(FULLMASK, a0 != 0.0f);
    const unsigned m1 = __ballot_sync(FULLMASK, a1 != 0.0f);

    // lane = feature-group: [0,16) -> sf1, [16,32) -> sf2
    const float4* src = (lane < 16)
        ? (const float4*)sf1 + rowOff * (FE / 4) + lane
        : (const float4*)sf2 + rowOff * (FE / 4) + (lane - 16);

    float4 acc = make_float4(0.f, 0.f, 0.f, 0.f);

    #pragma unroll
    for (int mb = 0; mb < 2; ++mb) {
        unsigned m   = mb ? m1 : m0;
        const float areg = mb ? a1 : a0;
        const int joff   = jbase + mb * 32;
        const int cnt    = __popc(m);

        for (int it = 0; it < cnt; it += 4) {
            const int take = cnt - it;        // >=1, uniform across warp
            int   jj[4];
            float aj[4];
            float4 v[4];
            #pragma unroll
            for (int u = 0; u < 4; ++u) {
                if (u < take) { jj[u] = __ffs(m) - 1; m &= m - 1; }
                else          { jj[u] = 0; }
            }
            #pragma unroll
            for (int u = 0; u < 4; ++u)
                aj[u] = (u < take) ? __shfl_sync(FULLMASK, areg, jj[u]) : 0.f;
            #pragma unroll
            for (int u = 0; u < 4; ++u)
                v[u] = __ldg(src + (long)(joff + jj[u]) * (FE / 4));
            #pragma unroll
            for (int u = 0; u < 4; ++u)
                acc = f4fma(acc, aj[u], v[u]);
        }
    }
    ((float4*)part)[(r * 2 + c) * (FTOT / 4) + lane] = acc;

    __syncthreads();

    // ---- reduce 2 half-partials per row; degrees ----
    #pragma unroll
    for (int k = 0; k < 2; ++k) {
        const int idx = tid + k * NT;         // 0..511
        const int r2  = idx >> 7;
        const int f   = idx & 127;
        Ssh[idx] = part[(r2 * 2) * FTOT + f] + part[(r2 * 2 + 1) * FTOT + f];
    }
    if (tid < ROWS) degS[tid] = degp[2 * tid] + degp[2 * tid + 1];
    __syncthreads();

    // ---- epilogue: o = tid&127; f-range split by tid>>7; 4 rows per W load --
    {
        const int o = tid & 127;
        const int h = tid >> 7;               // f-half
        float acc4[4] = {0.f, 0.f, 0.f, 0.f};
        const float* Wp = weight + (h * 64) * FOUT + o;
        #pragma unroll 8
        for (int f = 0; f < 64; ++f) {
            const float wv = __ldg(Wp + f * FOUT);
            const int  fg  = h * 64 + f;
            acc4[0] = fmaf(Ssh[0 * FTOT + fg], wv, acc4[0]);
            acc4[1] = fmaf(Ssh[1 * FTOT + fg], wv, acc4[1]);
            acc4[2] = fmaf(Ssh[2 * FTOT + fg], wv, acc4[2]);
            acc4[3] = fmaf(Ssh[3 * FTOT + fg], wv, acc4[3]);
        }
        #pragma unroll
        for (int rr = 0; rr < 4; ++rr)
            part[h * 512 + rr * FTOT + o] = acc4[rr];
    }
    __syncthreads();

    // ---- combine halves, bias*deg, relu, store ----
    #pragma unroll
    for (int k = 0; k < 2; ++k) {
        const int idx = tid + k * NT;         // 0..511 = rr*128 + o
        const int rr  = idx >> 7;
        const int o   = idx & 127;
        float v = part[idx] + part[512 + idx]
                + __ldg(bias + o) * degS[rr];
        out[(long)(row0 + rr) * FOUT + o] = fmaxf(v, 0.f);
    }
}

extern "C" void kernel_launch(void* const* d_in, const int* in_sizes, int n_in,
                              void* d_out, int out_size)
{
    const float* sf1    = (const float*)d_in[0];
    const float* sf2    = (const float*)d_in[1];
    const float* adj    = (const float*)d_in[2];
    const float* weight = (const float*)d_in[3];
    const float* bias   = (const float*)d_in[4];
    float* out          = (float*)d_out;

    gcn_sparse_kernel<<<NROWS / ROWS, NT>>>(sf1, sf2, adj, weight, bias, out);
}